// round 14
// baseline (speedup 1.0000x reference)
#include <cuda_runtime.h>
#include <cuda_bf16.h>
#include <cuda_fp16.h>

#define HH   1024
#define WW   1024
#define RAD  40
#define EPSF 1e-3f
#define MAXIMG 12
#define HWSZ (HH * WW)
#define SEG  128         // rows per thread in vertical sliding passes
#define UNRV 8           // unroll in vertical passes
#define TPBV 64          // threads per block, vertical passes (1 col/thread)

#define PADL 40          // left padding (zeros) in csp
#define CSPN 1112        // PADL + 1024 + 48 right padding

// ---------------------------------------------------------------------------
// Scratch (static __device__ arrays -- no runtime allocation).
// Intermediates fp16 (inputs centered at 0 -> variance math insensitive to
// storage rounding).
// ---------------------------------------------------------------------------
__device__ uint2    g_V4h [MAXIMG * HWSZ];   // vert sums (I',p',I'p',I'I') 8B/px
__device__ unsigned g_abh [MAXIMG * HWSZ];   // (a,b) half2 4B/px
__device__ unsigned g_sabh[MAXIMG * HWSZ];   // vert sums (a,b) half2 4B/px

static __device__ __forceinline__ unsigned pack2(float a, float b)
{
    __half2 h = __floats2half2_rn(a, b);
    return *reinterpret_cast<unsigned*>(&h);
}
static __device__ __forceinline__ float2 unpack2(unsigned u)
{
    return __half22float2(*reinterpret_cast<__half2*>(&u));
}

// ---------------------------------------------------------------------------
// Stage 1 vertical: sliding column sums of (I', p', I'p', I'I'),  X' = X-0.5
// grid = (HH/SEG, WW/TPBV, nimg)  -- y-segment varies FASTEST so adjacent
// blocks share halo rows in L2.  block = TPBV
// ---------------------------------------------------------------------------
__global__ __launch_bounds__(TPBV)
void vpassA(const float* __restrict__ I, const float* __restrict__ P)
{
    int col = blockIdx.y * TPBV + threadIdx.x;
    int y0  = blockIdx.x * SEG;
    size_t base = (size_t)blockIdx.z * HWSZ + col;

    const float* __restrict__ Ic = I + base;
    const float* __restrict__ Pc = P + base;
    uint2* __restrict__ V = g_V4h + base;

    float sI = 0.f, sP = 0.f, sIP = 0.f, sII = 0.f;
    int ys = max(y0 - RAD, 0);
    int ye = min(y0 + RAD, HH - 1);
#pragma unroll 4
    for (int y = ys; y <= ye; y++) {
        float i = Ic[(size_t)y * WW] - 0.5f;
        float p = Pc[(size_t)y * WW] - 0.5f;
        sI += i; sP += p; sIP += i * p; sII += i * i;
    }

    for (int yb = y0; yb < y0 + SEG; yb += UNRV) {
        float ai[UNRV], ap[UNRV], si[UNRV], sp[UNRV];
#pragma unroll
        for (int u = 0; u < UNRV; u++) {
            int ya = yb + u + RAD + 1;
            int yu = yb + u - RAD;
            ai[u] = (ya < HH) ? Ic[(size_t)ya * WW] - 0.5f : 0.f;
            ap[u] = (ya < HH) ? Pc[(size_t)ya * WW] - 0.5f : 0.f;
            si[u] = (yu >= 0) ? Ic[(size_t)yu * WW] - 0.5f : 0.f;
            sp[u] = (yu >= 0) ? Pc[(size_t)yu * WW] - 0.5f : 0.f;
        }
#pragma unroll
        for (int u = 0; u < UNRV; u++) {
            int y = yb + u;
            uint2 uu;
            uu.x = pack2(sI, sP);
            uu.y = pack2(sIP, sII);
            V[(size_t)y * WW] = uu;
            sI  += ai[u] - si[u];
            sP  += ap[u] - sp[u];
            sIP += ai[u] * ap[u] - si[u] * sp[u];
            sII += ai[u] * ai[u] - si[u] * si[u];
        }
    }
}

// ---------------------------------------------------------------------------
// Stage 1 horizontal: row prefix-scan of V4h (4 quantities), padded csp,
// conflict-free vectorized LDS; fused a/b -> abh.
// grid = (HH, nimg), block = 256
// ---------------------------------------------------------------------------
__global__ __launch_bounds__(256)
void hpassA()
{
    __shared__ float csp[4][CSPN];
    __shared__ float wsum[4][8];

    int t    = threadIdx.x;
    int lane = t & 31;
    int warp = t >> 5;
    int row  = blockIdx.x;
    size_t base = ((size_t)blockIdx.y * HH + row) * WW;
    size_t off  = base + (size_t)t * 4;

    uint4 r0 = __ldcs((const uint4*)(g_V4h + off));
    uint4 r1 = __ldcs((const uint4*)(g_V4h + off + 2));

    float2 p0a = unpack2(r0.x), p0b = unpack2(r0.y);
    float2 p1a = unpack2(r0.z), p1b = unpack2(r0.w);
    float2 p2a = unpack2(r1.x), p2b = unpack2(r1.y);
    float2 p3a = unpack2(r1.z), p3b = unpack2(r1.w);

    float e[4][4] = {
        { p0a.x, p1a.x, p2a.x, p3a.x },   // sI'
        { p0a.y, p1a.y, p2a.y, p3a.y },   // sP'
        { p0b.x, p1b.x, p2b.x, p3b.x },   // sI'P'
        { p0b.y, p1b.y, p2b.y, p3b.y }    // sI'I'
    };

    float loc[4][4], v[4];
#pragma unroll
    for (int q = 0; q < 4; q++) {
        loc[q][0] = e[q][0];
        loc[q][1] = loc[q][0] + e[q][1];
        loc[q][2] = loc[q][1] + e[q][2];
        loc[q][3] = loc[q][2] + e[q][3];
        v[q] = loc[q][3];
    }

#pragma unroll
    for (int d = 1; d < 32; d <<= 1) {
#pragma unroll
        for (int q = 0; q < 4; q++) {
            float n = __shfl_up_sync(0xffffffffu, v[q], d);
            if (lane >= d) v[q] += n;
        }
    }
    if (lane == 31) {
#pragma unroll
        for (int q = 0; q < 4; q++) wsum[q][warp] = v[q];
    }
    __syncthreads();

    int x = t * 4;
#pragma unroll
    for (int q = 0; q < 4; q++) {
        float wb = 0.f;
#pragma unroll
        for (int w2 = 0; w2 < 7; w2++)
            wb += (w2 < warp) ? wsum[q][w2] : 0.f;
        float excl = wb + v[q] - loc[q][3];
        *(float4*)&csp[q][PADL + x] =
            make_float4(excl, excl + loc[q][0], excl + loc[q][1], excl + loc[q][2]);
        if (t < 10)
            *(float4*)&csp[q][t * 4] = make_float4(0.f, 0.f, 0.f, 0.f);
        if (t >= 240 && t < 252) {
            float tot = wsum[q][0] + wsum[q][1] + wsum[q][2] + wsum[q][3]
                      + wsum[q][4] + wsum[q][5] + wsum[q][6] + wsum[q][7];
            *(float4*)&csp[q][PADL + WW + (t - 240) * 4] =
                make_float4(tot, tot, tot, tot);
        }
    }
    __syncthreads();

    float cy = (float)(min(row + RAD, HH - 1) - max(row - RAD, 0) + 1);

    float B[4][4];
#pragma unroll
    for (int q = 0; q < 4; q++) {
        float4 L  = *(const float4*)&csp[q][PADL + x - RAD];
        float4 HA = *(const float4*)&csp[q][PADL + x + RAD];
        float4 HB = *(const float4*)&csp[q][PADL + x + RAD + 4];
        B[q][0] = HA.y - L.x;
        B[q][1] = HA.z - L.y;
        B[q][2] = HA.w - L.z;
        B[q][3] = HB.x - L.w;
    }

    uint4 outv;
    unsigned* ov = &outv.x;
#pragma unroll
    for (int k = 0; k < 4; k++) {
        float cx  = (float)(min(x + k + RAD, WW - 1) - max(x + k - RAD, 0) + 1);
        float inv = 1.0f / (cx * cy);

        float mIc = B[0][k] * inv;
        float mPc = B[1][k] * inv;
        float cov = B[2][k] * inv - mIc * mPc;
        float var = B[3][k] * inv - mIc * mIc;
        float a   = cov / (var + EPSF);
        float b   = (mPc + 0.5f) - a * (mIc + 0.5f);
        ov[k] = pack2(a, b);
    }
    *(uint4*)(g_abh + off) = outv;
}

// ---------------------------------------------------------------------------
// Stage 2 vertical: sliding column sums of (a, b) from abh -> sabh.
// grid = (HH/SEG, WW/TPBV, nimg) -- y-segment fastest for halo L2 reuse.
// block = TPBV
// ---------------------------------------------------------------------------
__global__ __launch_bounds__(TPBV)
void vpassB()
{
    int col = blockIdx.y * TPBV + threadIdx.x;
    int y0  = blockIdx.x * SEG;
    size_t base = (size_t)blockIdx.z * HWSZ + col;

    const unsigned* __restrict__ A = g_abh + base;
    unsigned*       __restrict__ S = g_sabh + base;

    float sa = 0.f, sb = 0.f;
    int ys = max(y0 - RAD, 0);
    int ye = min(y0 + RAD, HH - 1);
#pragma unroll 4
    for (int y = ys; y <= ye; y++) {
        float2 v = unpack2(A[(size_t)y * WW]);
        sa += v.x; sb += v.y;
    }

    for (int yb = y0; yb < y0 + SEG; yb += UNRV) {
        unsigned addr[UNRV], subr[UNRV];
#pragma unroll
        for (int u = 0; u < UNRV; u++) {
            int ya = yb + u + RAD + 1;
            int yu = yb + u - RAD;
            addr[u] = (ya < HH) ? A[(size_t)ya * WW] : 0u;
            subr[u] = (yu >= 0) ? A[(size_t)yu * WW] : 0u;
        }
#pragma unroll
        for (int u = 0; u < UNRV; u++) {
            int y = yb + u;
            S[(size_t)y * WW] = pack2(sa, sb);
            float2 av = unpack2(addr[u]);
            float2 sv = unpack2(subr[u]);
            sa += av.x - sv.x;
            sb += av.y - sv.y;
        }
    }
}

// ---------------------------------------------------------------------------
// Stage 2 horizontal: row scan of (sum_a, sum_b), padded csp, final output.
// out = mean_a * I + mean_b
// grid = (HH, nimg), block = 256
// ---------------------------------------------------------------------------
__global__ __launch_bounds__(256)
void hpassB(const float* __restrict__ I, float* __restrict__ out)
{
    __shared__ float csp[2][CSPN];
    __shared__ float wsum[2][8];

    int t    = threadIdx.x;
    int lane = t & 31;
    int warp = t >> 5;
    int row  = blockIdx.x;
    size_t base = ((size_t)blockIdx.y * HH + row) * WW;
    size_t off  = base + (size_t)t * 4;

    uint4 r0 = __ldcs((const uint4*)(g_sabh + off));
    float2 s0 = unpack2(r0.x);
    float2 s1 = unpack2(r0.y);
    float2 s2 = unpack2(r0.z);
    float2 s3 = unpack2(r0.w);

    float e[2][4] = {
        { s0.x, s1.x, s2.x, s3.x },   // sum_a
        { s0.y, s1.y, s2.y, s3.y }    // sum_b
    };

    float loc[2][4], v[2];
#pragma unroll
    for (int q = 0; q < 2; q++) {
        loc[q][0] = e[q][0];
        loc[q][1] = loc[q][0] + e[q][1];
        loc[q][2] = loc[q][1] + e[q][2];
        loc[q][3] = loc[q][2] + e[q][3];
        v[q] = loc[q][3];
    }

#pragma unroll
    for (int d = 1; d < 32; d <<= 1) {
#pragma unroll
        for (int q = 0; q < 2; q++) {
            float n = __shfl_up_sync(0xffffffffu, v[q], d);
            if (lane >= d) v[q] += n;
        }
    }
    if (lane == 31) {
#pragma unroll
        for (int q = 0; q < 2; q++) wsum[q][warp] = v[q];
    }
    __syncthreads();

    int x = t * 4;
#pragma unroll
    for (int q = 0; q < 2; q++) {
        float wb = 0.f;
#pragma unroll
        for (int w2 = 0; w2 < 7; w2++)
            wb += (w2 < warp) ? wsum[q][w2] : 0.f;
        float excl = wb + v[q] - loc[q][3];
        *(float4*)&csp[q][PADL + x] =
            make_float4(excl, excl + loc[q][0], excl + loc[q][1], excl + loc[q][2]);
        if (t < 10)
            *(float4*)&csp[q][t * 4] = make_float4(0.f, 0.f, 0.f, 0.f);
        if (t >= 240 && t < 252) {
            float tot = wsum[q][0] + wsum[q][1] + wsum[q][2] + wsum[q][3]
                      + wsum[q][4] + wsum[q][5] + wsum[q][6] + wsum[q][7];
            *(float4*)&csp[q][PADL + WW + (t - 240) * 4] =
                make_float4(tot, tot, tot, tot);
        }
    }
    __syncthreads();

    float cy = (float)(min(row + RAD, HH - 1) - max(row - RAD, 0) + 1);
    float4 vI = __ldcs((const float4*)(I + off));
    float iv[4] = { vI.x, vI.y, vI.z, vI.w };

    float B[2][4];
#pragma unroll
    for (int q = 0; q < 2; q++) {
        float4 L  = *(const float4*)&csp[q][PADL + x - RAD];
        float4 HA = *(const float4*)&csp[q][PADL + x + RAD];
        float4 HB = *(const float4*)&csp[q][PADL + x + RAD + 4];
        B[q][0] = HA.y - L.x;
        B[q][1] = HA.z - L.y;
        B[q][2] = HA.w - L.z;
        B[q][3] = HB.x - L.w;
    }

    float4 o;
    float* op = &o.x;
#pragma unroll
    for (int k = 0; k < 4; k++) {
        float cx  = (float)(min(x + k + RAD, WW - 1) - max(x + k - RAD, 0) + 1);
        float inv = 1.0f / (cx * cy);
        op[k] = (B[0][k] * inv) * iv[k] + (B[1][k] * inv);
    }
    __stcs((float4*)(out + off), o);
}

// ---------------------------------------------------------------------------
extern "C" void kernel_launch(void* const* d_in, const int* in_sizes, int n_in,
                              void* d_out, int out_size)
{
    const float* I = (const float*)d_in[0];
    const float* P = (const float*)d_in[1];
    float* out     = (float*)d_out;

    int nimg = in_sizes[0] / HWSZ;      // B*C images of 1024x1024
    if (nimg > MAXIMG) nimg = MAXIMG;

    dim3 hgrid(HH, nimg);
    dim3 vgrid(HH / SEG, WW / TPBV, nimg);   // y-segment fastest

    vpassA<<<vgrid, TPBV>>>(I, P);
    hpassA<<<hgrid, 256>>>();
    vpassB<<<vgrid, TPBV>>>();
    hpassB<<<hgrid, 256>>>(I, out);
}

// round 15
// speedup vs baseline: 1.1199x; 1.1199x over previous
#include <cuda_runtime.h>
#include <cuda_bf16.h>
#include <cuda_fp16.h>

#define HH   1024
#define WW   1024
#define RAD  40
#define EPSF 1e-3f
#define MAXIMG 12
#define HWSZ (HH * WW)
#define SEG  128         // rows per thread in vertical sliding passes
#define UNRV 8           // unroll in vertical passes
#define TPBV 64          // threads per block, vertical passes (1 col/thread)

#define PADL 40          // left padding (zeros) in csp
#define CSPN 1112        // PADL + 1024 + 48 right padding

// ---------------------------------------------------------------------------
// Scratch (static __device__ arrays -- no runtime allocation).
// Intermediates fp16 (inputs centered at 0 -> variance math insensitive to
// storage rounding).
//   g_H4h : HORIZONTAL box sums of (I',p',I'p',I'I')  8B/px (2x half2)
//   g_abh : (a,b) half2 4B/px
//   g_sabh: vertical box sums of (a,b) half2 4B/px
// ---------------------------------------------------------------------------
__device__ uint2    g_H4h [MAXIMG * HWSZ];
__device__ unsigned g_abh [MAXIMG * HWSZ];
__device__ unsigned g_sabh[MAXIMG * HWSZ];

static __device__ __forceinline__ unsigned pack2(float a, float b)
{
    __half2 h = __floats2half2_rn(a, b);
    return *reinterpret_cast<unsigned*>(&h);
}
static __device__ __forceinline__ float2 unpack2(unsigned u)
{
    return __half22float2(*reinterpret_cast<__half2*>(&u));
}

// ---------------------------------------------------------------------------
// Stage 1 horizontal (FIRST): row prefix-scan of raw (I',p',I'p',I'I'),
// padded csp, conflict-free vectorized LDS; horizontal box SUMS -> g_H4h.
// grid = (HH, nimg), block = 256
// ---------------------------------------------------------------------------
__global__ __launch_bounds__(256)
void hpass1(const float* __restrict__ I, const float* __restrict__ P)
{
    __shared__ float csp[4][CSPN];
    __shared__ float wsum[4][8];

    int t    = threadIdx.x;
    int lane = t & 31;
    int warp = t >> 5;
    int row  = blockIdx.x;
    size_t base = ((size_t)blockIdx.y * HH + row) * WW;
    size_t off  = base + (size_t)t * 4;

    float4 vI = *(const float4*)(I + off);
    float4 vP = *(const float4*)(P + off);
    vI.x -= 0.5f; vI.y -= 0.5f; vI.z -= 0.5f; vI.w -= 0.5f;
    vP.x -= 0.5f; vP.y -= 0.5f; vP.z -= 0.5f; vP.w -= 0.5f;

    float e[4][4] = {
        { vI.x, vI.y, vI.z, vI.w },                             // I'
        { vP.x, vP.y, vP.z, vP.w },                             // p'
        { vI.x * vP.x, vI.y * vP.y, vI.z * vP.z, vI.w * vP.w }, // I'p'
        { vI.x * vI.x, vI.y * vI.y, vI.z * vI.z, vI.w * vI.w }  // I'I'
    };

    float loc[4][4], v[4];
#pragma unroll
    for (int q = 0; q < 4; q++) {
        loc[q][0] = e[q][0];
        loc[q][1] = loc[q][0] + e[q][1];
        loc[q][2] = loc[q][1] + e[q][2];
        loc[q][3] = loc[q][2] + e[q][3];
        v[q] = loc[q][3];
    }

#pragma unroll
    for (int d = 1; d < 32; d <<= 1) {
#pragma unroll
        for (int q = 0; q < 4; q++) {
            float n = __shfl_up_sync(0xffffffffu, v[q], d);
            if (lane >= d) v[q] += n;
        }
    }
    if (lane == 31) {
#pragma unroll
        for (int q = 0; q < 4; q++) wsum[q][warp] = v[q];
    }
    __syncthreads();

    int x = t * 4;
#pragma unroll
    for (int q = 0; q < 4; q++) {
        float wb = 0.f;
#pragma unroll
        for (int w2 = 0; w2 < 7; w2++)
            wb += (w2 < warp) ? wsum[q][w2] : 0.f;
        float excl = wb + v[q] - loc[q][3];
        *(float4*)&csp[q][PADL + x] =
            make_float4(excl, excl + loc[q][0], excl + loc[q][1], excl + loc[q][2]);
        if (t < 10)
            *(float4*)&csp[q][t * 4] = make_float4(0.f, 0.f, 0.f, 0.f);
        if (t >= 240 && t < 252) {
            float tot = wsum[q][0] + wsum[q][1] + wsum[q][2] + wsum[q][3]
                      + wsum[q][4] + wsum[q][5] + wsum[q][6] + wsum[q][7];
            *(float4*)&csp[q][PADL + WW + (t - 240) * 4] =
                make_float4(tot, tot, tot, tot);
        }
    }
    __syncthreads();

    float B[4][4];
#pragma unroll
    for (int q = 0; q < 4; q++) {
        float4 L  = *(const float4*)&csp[q][PADL + x - RAD];
        float4 HA = *(const float4*)&csp[q][PADL + x + RAD];
        float4 HB = *(const float4*)&csp[q][PADL + x + RAD + 4];
        B[q][0] = HA.y - L.x;
        B[q][1] = HA.z - L.y;
        B[q][2] = HA.w - L.z;
        B[q][3] = HB.x - L.w;
    }

    // pack horizontal box sums: px k -> uint2{ (hsI,hsP), (hsIP,hsII) }
    uint4 w0, w1;
    w0.x = pack2(B[0][0], B[1][0]);  w0.y = pack2(B[2][0], B[3][0]);
    w0.z = pack2(B[0][1], B[1][1]);  w0.w = pack2(B[2][1], B[3][1]);
    w1.x = pack2(B[0][2], B[1][2]);  w1.y = pack2(B[2][2], B[3][2]);
    w1.z = pack2(B[0][3], B[1][3]);  w1.w = pack2(B[2][3], B[3][3]);
    *(uint4*)(g_H4h + off)     = w0;
    *(uint4*)(g_H4h + off + 2) = w1;
}

// ---------------------------------------------------------------------------
// Stage 1 vertical (SECOND): sliding column sums of the 4 h-sums completes
// the 2D box; fused a/b computation -> g_abh.
// grid = (WW/TPBV, HH/SEG, nimg), block = TPBV
// ---------------------------------------------------------------------------
__global__ __launch_bounds__(TPBV)
void vpass1()
{
    int col = blockIdx.x * TPBV + threadIdx.x;
    int y0  = blockIdx.y * SEG;
    size_t base = (size_t)blockIdx.z * HWSZ + col;

    const uint2* __restrict__ Hc = g_H4h + base;
    unsigned*    __restrict__ Ab = g_abh + base;

    float sI = 0.f, sP = 0.f, sIP = 0.f, sII = 0.f;
    int ys = max(y0 - RAD, 0);
    int ye = min(y0 + RAD, HH - 1);
#pragma unroll 4
    for (int y = ys; y <= ye; y++) {
        uint2 r = Hc[(size_t)y * WW];
        float2 c0 = unpack2(r.x), c1 = unpack2(r.y);
        sI += c0.x; sP += c0.y; sIP += c1.x; sII += c1.y;
    }

    float cx = (float)(min(col + RAD, WW - 1) - max(col - RAD, 0) + 1);
    const uint2 z2 = make_uint2(0u, 0u);

    for (int yb = y0; yb < y0 + SEG; yb += UNRV) {
        uint2 addr[UNRV], subr[UNRV];
#pragma unroll
        for (int u = 0; u < UNRV; u++) {
            int ya = yb + u + RAD + 1;
            int yu = yb + u - RAD;
            addr[u] = (ya < HH) ? Hc[(size_t)ya * WW] : z2;
            subr[u] = (yu >= 0) ? Hc[(size_t)yu * WW] : z2;
        }
#pragma unroll
        for (int u = 0; u < UNRV; u++) {
            int y = yb + u;
            float cy  = (float)(min(y + RAD, HH - 1) - max(y - RAD, 0) + 1);
            float inv = 1.0f / (cx * cy);

            float mIc = sI  * inv;
            float mPc = sP  * inv;
            float cov = sIP * inv - mIc * mPc;
            float var = sII * inv - mIc * mIc;
            float a   = cov / (var + EPSF);
            float b   = (mPc + 0.5f) - a * (mIc + 0.5f);
            Ab[(size_t)y * WW] = pack2(a, b);

            float2 a0 = unpack2(addr[u].x), a1 = unpack2(addr[u].y);
            float2 u0 = unpack2(subr[u].x), u1 = unpack2(subr[u].y);
            sI  += a0.x - u0.x;
            sP  += a0.y - u0.y;
            sIP += a1.x - u1.x;
            sII += a1.y - u1.y;
        }
    }
}

// ---------------------------------------------------------------------------
// Stage 2 vertical: sliding column sums of (a, b) from abh -> sabh.
// grid = (WW/TPBV, HH/SEG, nimg), block = TPBV
// ---------------------------------------------------------------------------
__global__ __launch_bounds__(TPBV)
void vpassB()
{
    int col = blockIdx.x * TPBV + threadIdx.x;
    int y0  = blockIdx.y * SEG;
    size_t base = (size_t)blockIdx.z * HWSZ + col;

    const unsigned* __restrict__ A = g_abh + base;
    unsigned*       __restrict__ S = g_sabh + base;

    float sa = 0.f, sb = 0.f;
    int ys = max(y0 - RAD, 0);
    int ye = min(y0 + RAD, HH - 1);
#pragma unroll 4
    for (int y = ys; y <= ye; y++) {
        float2 v = unpack2(A[(size_t)y * WW]);
        sa += v.x; sb += v.y;
    }

    for (int yb = y0; yb < y0 + SEG; yb += UNRV) {
        unsigned addr[UNRV], subr[UNRV];
#pragma unroll
        for (int u = 0; u < UNRV; u++) {
            int ya = yb + u + RAD + 1;
            int yu = yb + u - RAD;
            addr[u] = (ya < HH) ? A[(size_t)ya * WW] : 0u;
            subr[u] = (yu >= 0) ? A[(size_t)yu * WW] : 0u;
        }
#pragma unroll
        for (int u = 0; u < UNRV; u++) {
            int y = yb + u;
            S[(size_t)y * WW] = pack2(sa, sb);
            float2 av = unpack2(addr[u]);
            float2 sv = unpack2(subr[u]);
            sa += av.x - sv.x;
            sb += av.y - sv.y;
        }
    }
}

// ---------------------------------------------------------------------------
// Stage 2 horizontal: row scan of (sum_a, sum_b), padded csp, final output.
// out = mean_a * I + mean_b
// grid = (HH, nimg), block = 256
// ---------------------------------------------------------------------------
__global__ __launch_bounds__(256)
void hpassB(const float* __restrict__ I, float* __restrict__ out)
{
    __shared__ float csp[2][CSPN];
    __shared__ float wsum[2][8];

    int t    = threadIdx.x;
    int lane = t & 31;
    int warp = t >> 5;
    int row  = blockIdx.x;
    size_t base = ((size_t)blockIdx.y * HH + row) * WW;
    size_t off  = base + (size_t)t * 4;

    uint4 r0 = __ldcs((const uint4*)(g_sabh + off));
    float2 s0 = unpack2(r0.x);
    float2 s1 = unpack2(r0.y);
    float2 s2 = unpack2(r0.z);
    float2 s3 = unpack2(r0.w);

    float e[2][4] = {
        { s0.x, s1.x, s2.x, s3.x },   // sum_a
        { s0.y, s1.y, s2.y, s3.y }    // sum_b
    };

    float loc[2][4], v[2];
#pragma unroll
    for (int q = 0; q < 2; q++) {
        loc[q][0] = e[q][0];
        loc[q][1] = loc[q][0] + e[q][1];
        loc[q][2] = loc[q][1] + e[q][2];
        loc[q][3] = loc[q][2] + e[q][3];
        v[q] = loc[q][3];
    }

#pragma unroll
    for (int d = 1; d < 32; d <<= 1) {
#pragma unroll
        for (int q = 0; q < 2; q++) {
            float n = __shfl_up_sync(0xffffffffu, v[q], d);
            if (lane >= d) v[q] += n;
        }
    }
    if (lane == 31) {
#pragma unroll
        for (int q = 0; q < 2; q++) wsum[q][warp] = v[q];
    }
    __syncthreads();

    int x = t * 4;
#pragma unroll
    for (int q = 0; q < 2; q++) {
        float wb = 0.f;
#pragma unroll
        for (int w2 = 0; w2 < 7; w2++)
            wb += (w2 < warp) ? wsum[q][w2] : 0.f;
        float excl = wb + v[q] - loc[q][3];
        *(float4*)&csp[q][PADL + x] =
            make_float4(excl, excl + loc[q][0], excl + loc[q][1], excl + loc[q][2]);
        if (t < 10)
            *(float4*)&csp[q][t * 4] = make_float4(0.f, 0.f, 0.f, 0.f);
        if (t >= 240 && t < 252) {
            float tot = wsum[q][0] + wsum[q][1] + wsum[q][2] + wsum[q][3]
                      + wsum[q][4] + wsum[q][5] + wsum[q][6] + wsum[q][7];
            *(float4*)&csp[q][PADL + WW + (t - 240) * 4] =
                make_float4(tot, tot, tot, tot);
        }
    }
    __syncthreads();

    float cy = (float)(min(row + RAD, HH - 1) - max(row - RAD, 0) + 1);
    float4 vI = __ldcs((const float4*)(I + off));
    float iv[4] = { vI.x, vI.y, vI.z, vI.w };

    float B[2][4];
#pragma unroll
    for (int q = 0; q < 2; q++) {
        float4 L  = *(const float4*)&csp[q][PADL + x - RAD];
        float4 HA = *(const float4*)&csp[q][PADL + x + RAD];
        float4 HB = *(const float4*)&csp[q][PADL + x + RAD + 4];
        B[q][0] = HA.y - L.x;
        B[q][1] = HA.z - L.y;
        B[q][2] = HA.w - L.z;
        B[q][3] = HB.x - L.w;
    }

    float4 o;
    float* op = &o.x;
#pragma unroll
    for (int k = 0; k < 4; k++) {
        float cx  = (float)(min(x + k + RAD, WW - 1) - max(x + k - RAD, 0) + 1);
        float inv = 1.0f / (cx * cy);
        op[k] = (B[0][k] * inv) * iv[k] + (B[1][k] * inv);
    }
    __stcs((float4*)(out + off), o);
}

// ---------------------------------------------------------------------------
extern "C" void kernel_launch(void* const* d_in, const int* in_sizes, int n_in,
                              void* d_out, int out_size)
{
    const float* I = (const float*)d_in[0];
    const float* P = (const float*)d_in[1];
    float* out     = (float*)d_out;

    int nimg = in_sizes[0] / HWSZ;      // B*C images of 1024x1024
    if (nimg > MAXIMG) nimg = MAXIMG;

    dim3 hgrid(HH, nimg);
    dim3 vgrid(WW / TPBV, HH / SEG, nimg);   // column-fastest (proven)

    hpass1<<<hgrid, 256>>>(I, P);
    vpass1<<<vgrid, TPBV>>>();
    vpassB<<<vgrid, TPBV>>>();
    hpassB<<<hgrid, 256>>>(I, out);
}